// round 1
// baseline (speedup 1.0000x reference)
#include <cuda_runtime.h>
#include <math.h>

// Fixed problem shape (from reference setup_inputs)
#define Bq 4
#define Sq 1024
#define Dq 256
#define Hq 6
#define HDq 64
#define Eq 3
#define NHq (Hq*HDq)     // 384
#define BSq (Bq*Sq)      // 4096
#define BSDq (BSq*Dq)    // 1048576

// ---------------- scratch (static device globals; no allocs allowed) ----------------
__device__ float g_h[Bq*Hq*Sq*HDq];     // per-expert head features [b][h][s][o]
__device__ float g_es[Bq*Hq*Sq];
__device__ float g_ed[Bq*Hq*Sq];
__device__ float g_hsum[Bq*Hq*HDq];     // sum over s of g_h (for empty-neighbor uniform case)
__device__ float g_h1[BSq*NHq];         // concat-head layer-1 output [b][s][h*HD+o]
__device__ float g_h2[BSDq];            // layer-2 features
__device__ float g_gs[BSq];
__device__ float g_gd[BSq];
__device__ float g_h2sum[Bq*Dq];
__device__ float g_main[BSDq];
__device__ float g_dep[BSDq];
__device__ float g_bw[BSDq];
__device__ float g_bwsum;
__device__ unsigned char g_rmask[Eq*BSq];

__device__ __forceinline__ float leaky02(float x) { return x > 0.f ? x : 0.2f * x; }
__device__ __forceinline__ float elu1(float x)    { return x > 0.f ? x : expm1f(x); }

// ---------------- zero init ----------------
__global__ void k_zero() {
    int i = blockIdx.x * 256 + threadIdx.x;
    if (i < BSDq) g_dep[i] = 0.f;
    if (i == 0) g_bwsum = 0.f;
}

// ---------------- router: top-2 of 3 => exclude argmin (last index on ties) ----------------
__global__ void k_router(const float* __restrict__ x, const float* __restrict__ Wr) {
    int gw   = (blockIdx.x * blockDim.x + threadIdx.x) >> 5;
    int lane = threadIdx.x & 31;
    if (gw >= BSq) return;
    const float* xr = x + (size_t)gw * Dq;
    float a0 = 0.f, a1 = 0.f, a2 = 0.f;
    for (int k = lane; k < Dq; k += 32) {
        float xv = xr[k];
        a0 += xv * Wr[k * 3 + 0];
        a1 += xv * Wr[k * 3 + 1];
        a2 += xv * Wr[k * 3 + 2];
    }
    #pragma unroll
    for (int o = 16; o > 0; o >>= 1) {
        a0 += __shfl_down_sync(0xffffffffu, a0, o);
        a1 += __shfl_down_sync(0xffffffffu, a1, o);
        a2 += __shfl_down_sync(0xffffffffu, a2, o);
    }
    if (lane == 0) {
        float v[3] = {a0, a1, a2};
        int ex = 0; float mv = v[0];
        #pragma unroll
        for (int e = 1; e < 3; e++) if (v[e] <= mv) { mv = v[e]; ex = e; }
        #pragma unroll
        for (int e = 0; e < 3; e++) g_rmask[e * BSq + gw] = (e == ex) ? 0 : 1;
    }
}

// ---------------- blend gate: sigmoid(x @ blend_W + b), plus global mean accumulation ----------
__global__ void k_blend(const float* __restrict__ x, const float* __restrict__ W,
                        const float* __restrict__ bias) {
    __shared__ float xs[Dq];
    __shared__ float red[256];
    int node = blockIdx.x;
    int d = threadIdx.x;
    xs[d] = x[(size_t)node * Dq + d];
    __syncthreads();
    float acc = 0.f;
    #pragma unroll 4
    for (int k = 0; k < Dq; k++) acc += xs[k] * W[k * Dq + d];
    float bw = 1.f / (1.f + expf(-(acc + bias[d])));
    g_bw[(size_t)node * Dq + d] = bw;
    red[d] = bw;
    __syncthreads();
    for (int st = 128; st > 0; st >>= 1) { if (d < st) red[d] += red[d + st]; __syncthreads(); }
    if (d == 0) atomicAdd(&g_bwsum, red[0]);
}

// ---------------- GEMM: g_h[b][h][s][o] = (x * rowmask) @ W1[h]  (M=1024,N=64/head,K=256) ----
__global__ void k_gemm_h(const float* __restrict__ X, const float* __restrict__ W1, int expert) {
    // grid (H, S/64, B), block 256 (logical 16x16, 4x4 microtile)
    int h = blockIdx.x, m0 = blockIdx.y * 64, b = blockIdx.z;
    int tid = threadIdx.x;
    int tx = tid & 15, ty = tid >> 4;
    __shared__ float As[32][65];
    __shared__ float Bs[32][65];
    float acc[4][4] = {};
    const float* Xb = X + (size_t)b * Sq * Dq;
    const float* Wb = W1 + (size_t)h * Dq * HDq;
    const unsigned char* mk = (expert >= 0) ? (g_rmask + (size_t)expert * BSq + (size_t)b * Sq) : nullptr;
    for (int k0 = 0; k0 < Dq; k0 += 32) {
        #pragma unroll
        for (int p = 0; p < 8; p++) {
            int midx = (tid >> 5) + p * 8;
            int kidx = tid & 31;
            float v = Xb[(size_t)(m0 + midx) * Dq + k0 + kidx];
            if (mk && mk[m0 + midx] == 0) v = 0.f;
            As[kidx][midx] = v;
        }
        #pragma unroll
        for (int p = 0; p < 8; p++) {
            int kidx = (tid >> 6) + p * 4;
            int o = tid & 63;
            Bs[kidx][o] = Wb[(size_t)(k0 + kidx) * HDq + o];
        }
        __syncthreads();
        #pragma unroll
        for (int kk = 0; kk < 32; kk++) {
            float av[4], bv[4];
            #pragma unroll
            for (int i = 0; i < 4; i++) av[i] = As[kk][ty * 4 + i];
            #pragma unroll
            for (int j = 0; j < 4; j++) bv[j] = Bs[kk][tx * 4 + j];
            #pragma unroll
            for (int i = 0; i < 4; i++)
                #pragma unroll
                for (int j = 0; j < 4; j++) acc[i][j] += av[i] * bv[j];
        }
        __syncthreads();
    }
    float* out = g_h + ((size_t)b * Hq + h) * Sq * HDq;
    #pragma unroll
    for (int i = 0; i < 4; i++)
        #pragma unroll
        for (int j = 0; j < 4; j++)
            out[(size_t)(m0 + ty * 4 + i) * HDq + tx * 4 + j] = acc[i][j];
}

// ---------------- es/ed per (b,h,s): 64-dot with a1s/a1d ----------------
__global__ void k_esed(const float* __restrict__ a1s, const float* __restrict__ a1d) {
    int gw   = (blockIdx.x * blockDim.x + threadIdx.x) >> 5;
    int lane = threadIdx.x & 31;
    if (gw >= Bq * Hq * Sq) return;
    int h = (gw / Sq) % Hq;
    const float* hr = g_h + (size_t)gw * HDq;
    float as = 0.f, ad = 0.f;
    #pragma unroll
    for (int o = lane; o < HDq; o += 32) {
        float v = hr[o];
        as += v * a1s[h * HDq + o];
        ad += v * a1d[h * HDq + o];
    }
    #pragma unroll
    for (int o = 16; o > 0; o >>= 1) {
        as += __shfl_down_sync(0xffffffffu, as, o);
        ad += __shfl_down_sync(0xffffffffu, ad, o);
    }
    if (lane == 0) { g_es[gw] = as; g_ed[gw] = ad; }
}

// ---------------- hsum[b][h][o] = sum_s g_h ----------------
__global__ void k_hsum() {
    int bh = blockIdx.x, o = threadIdx.x;
    const float* base = g_h + (size_t)bh * Sq * HDq;
    float s0 = 0.f, s1 = 0.f, s2 = 0.f, s3 = 0.f;
    for (int t = 0; t < Sq; t += 4) {
        s0 += base[(size_t)t * HDq + o];
        s1 += base[(size_t)(t + 1) * HDq + o];
        s2 += base[(size_t)(t + 2) * HDq + o];
        s3 += base[(size_t)(t + 3) * HDq + o];
    }
    g_hsum[bh * HDq + o] = (s0 + s1) + (s2 + s3);
}

// ---------------- attention layer 1 (all heads per block, compacted neighbor list) ----------
__global__ void k_att1(const float* __restrict__ adj, const int* __restrict__ dnum,
                       const int* __restrict__ snum, int expert) {
    __shared__ unsigned short lst[Sq];
    __shared__ float w[Sq];
    __shared__ float red[128];
    __shared__ int cnt;
    int b = blockIdx.x >> 10, s = blockIdx.x & 1023;
    int tid = threadIdx.x;  // 128
    if (tid == 0) cnt = 0;
    __syncthreads();
    int doc = dnum[0], sect = snum[0];
    int lo = 0, hi = Sq;
    if (expert == 0)      { lo = 0;              hi = Sq - sect - doc; }
    else if (expert == 1) { lo = Sq - sect - doc; hi = Sq - doc; }
    else if (expert == 2) { lo = Sq - doc;        hi = Sq; }
    const float* arow = adj + ((size_t)b * Sq + s) * Sq;
    for (int t = lo + tid; t < hi; t += 128)
        if (arow[t] > 0.f) { int p = atomicAdd(&cnt, 1); lst[p] = (unsigned short)t; }
    __syncthreads();
    int n = cnt;
    float* h1row = g_h1 + ((size_t)b * Sq + s) * NHq;
    for (int h = 0; h < Hq; h++) {
        size_t bhS = ((size_t)b * Hq + h) * Sq;
        if (n > 0) {
            float es = g_es[bhS + s];
            float lmax = -1e30f;
            for (int j = tid; j < n; j += 128) {
                float e = leaky02(es + g_ed[bhS + lst[j]]);
                w[j] = e;
                lmax = fmaxf(lmax, e);
            }
            red[tid] = lmax; __syncthreads();
            for (int st = 64; st > 0; st >>= 1) { if (tid < st) red[tid] = fmaxf(red[tid], red[tid + st]); __syncthreads(); }
            float m = red[0]; __syncthreads();
            float lsum = 0.f;
            for (int j = tid; j < n; j += 128) { float ww = expf(w[j] - m); w[j] = ww; lsum += ww; }
            red[tid] = lsum; __syncthreads();
            for (int st = 64; st > 0; st >>= 1) { if (tid < st) red[tid] += red[tid + st]; __syncthreads(); }
            float denom = red[0]; __syncthreads();
            int o = tid & 63, half = tid >> 6;
            const float* hb = g_h + bhS * HDq;
            float acc = 0.f;
            for (int j = half; j < n; j += 2) acc += w[j] * hb[(size_t)lst[j] * HDq + o];
            red[tid] = acc; __syncthreads();
            if (tid < 64) h1row[h * HDq + tid] = elu1((red[tid] + red[tid + 64]) / denom);
            __syncthreads();
        } else {
            // all masked -> softmax of all -1e9 -> uniform 1/S over ALL columns
            if (tid < 64) h1row[h * HDq + tid] = elu1(g_hsum[(b * Hq + h) * HDq + tid] * (1.f / Sq));
            __syncthreads();
        }
    }
}

// ---------------- GEMM: g_h2 = g_h1 @ W2 (M=1024,N=256,K=384) ----------------
__global__ void k_gemm_h2(const float* __restrict__ W2) {
    int n0 = blockIdx.x * 64, m0 = blockIdx.y * 64, b = blockIdx.z;
    int tid = threadIdx.x;
    int tx = tid & 15, ty = tid >> 4;
    __shared__ float As[32][65];
    __shared__ float Bs[32][65];
    float acc[4][4] = {};
    const float* Ab = g_h1 + (size_t)b * Sq * NHq;
    for (int k0 = 0; k0 < NHq; k0 += 32) {
        #pragma unroll
        for (int p = 0; p < 8; p++) {
            int midx = (tid >> 5) + p * 8;
            int kidx = tid & 31;
            As[kidx][midx] = Ab[(size_t)(m0 + midx) * NHq + k0 + kidx];
        }
        #pragma unroll
        for (int p = 0; p < 8; p++) {
            int kidx = (tid >> 6) + p * 4;
            int o = tid & 63;
            Bs[kidx][o] = W2[(size_t)(k0 + kidx) * Dq + n0 + o];
        }
        __syncthreads();
        #pragma unroll
        for (int kk = 0; kk < 32; kk++) {
            float av[4], bv[4];
            #pragma unroll
            for (int i = 0; i < 4; i++) av[i] = As[kk][ty * 4 + i];
            #pragma unroll
            for (int j = 0; j < 4; j++) bv[j] = Bs[kk][tx * 4 + j];
            #pragma unroll
            for (int i = 0; i < 4; i++)
                #pragma unroll
                for (int j = 0; j < 4; j++) acc[i][j] += av[i] * bv[j];
        }
        __syncthreads();
    }
    #pragma unroll
    for (int i = 0; i < 4; i++)
        #pragma unroll
        for (int j = 0; j < 4; j++)
            g_h2[((size_t)b * Sq + m0 + ty * 4 + i) * Dq + n0 + tx * 4 + j] = acc[i][j];
}

// ---------------- gs/gd per (b,s): 256-dot with a2s/a2d ----------------
__global__ void k_gsgd(const float* __restrict__ a2s, const float* __restrict__ a2d) {
    int gw   = (blockIdx.x * blockDim.x + threadIdx.x) >> 5;
    int lane = threadIdx.x & 31;
    if (gw >= BSq) return;
    const float* hr = g_h2 + (size_t)gw * Dq;
    float as = 0.f, ad = 0.f;
    #pragma unroll
    for (int k = lane; k < Dq; k += 32) {
        float v = hr[k];
        as += v * a2s[k];
        ad += v * a2d[k];
    }
    #pragma unroll
    for (int o = 16; o > 0; o >>= 1) {
        as += __shfl_down_sync(0xffffffffu, as, o);
        ad += __shfl_down_sync(0xffffffffu, ad, o);
    }
    if (lane == 0) { g_gs[gw] = as; g_gd[gw] = ad; }
}

// ---------------- h2sum[b][d] = sum_s g_h2 ----------------
__global__ void k_h2sum() {
    int b = blockIdx.x, d = threadIdx.x;
    const float* base = g_h2 + (size_t)b * Sq * Dq;
    float s0 = 0.f, s1 = 0.f, s2 = 0.f, s3 = 0.f;
    for (int t = 0; t < Sq; t += 4) {
        s0 += base[(size_t)t * Dq + d];
        s1 += base[(size_t)(t + 1) * Dq + d];
        s2 += base[(size_t)(t + 2) * Dq + d];
        s3 += base[(size_t)(t + 3) * Dq + d];
    }
    g_h2sum[b * Dq + d] = (s0 + s1) + (s2 + s3);
}

// ---------------- attention layer 2 ----------------
__global__ void k_att2(const float* __restrict__ adj, const int* __restrict__ dnum,
                       const int* __restrict__ snum, int expert) {
    __shared__ unsigned short lst[Sq];
    __shared__ float w[Sq];
    __shared__ float red[256];
    __shared__ int cnt;
    int b = blockIdx.x >> 10, s = blockIdx.x & 1023;
    int tid = threadIdx.x;  // 256
    if (expert >= 0) {
        // deputy output is row-masked; skip unrouted rows entirely
        if (g_rmask[(size_t)expert * BSq + blockIdx.x] == 0) return;
    }
    if (tid == 0) cnt = 0;
    __syncthreads();
    int doc = dnum[0], sect = snum[0];
    int lo = 0, hi = Sq;
    if (expert == 0)      { lo = 0;              hi = Sq - sect - doc; }
    else if (expert == 1) { lo = Sq - sect - doc; hi = Sq - doc; }
    else if (expert == 2) { lo = Sq - doc;        hi = Sq; }
    const float* arow = adj + ((size_t)b * Sq + s) * Sq;
    for (int t = lo + tid; t < hi; t += 256)
        if (arow[t] > 0.f) { int p = atomicAdd(&cnt, 1); lst[p] = (unsigned short)t; }
    __syncthreads();
    int n = cnt;
    float outv;
    if (n > 0) {
        float gs = g_gs[blockIdx.x];
        float lmax = -1e30f;
        for (int j = tid; j < n; j += 256) {
            float e = leaky02(gs + g_gd[(size_t)b * Sq + lst[j]]);
            w[j] = e;
            lmax = fmaxf(lmax, e);
        }
        red[tid] = lmax; __syncthreads();
        for (int st = 128; st > 0; st >>= 1) { if (tid < st) red[tid] = fmaxf(red[tid], red[tid + st]); __syncthreads(); }
        float m = red[0]; __syncthreads();
        float lsum = 0.f;
        for (int j = tid; j < n; j += 256) { float ww = expf(w[j] - m); w[j] = ww; lsum += ww; }
        red[tid] = lsum; __syncthreads();
        for (int st = 128; st > 0; st >>= 1) { if (tid < st) red[tid] += red[tid + st]; __syncthreads(); }
        float inv = 1.f / red[0]; __syncthreads();
        const float* h2b = g_h2 + (size_t)b * Sq * Dq;
        float acc = 0.f;
        for (int j = 0; j < n; j++) acc += w[j] * h2b[(size_t)lst[j] * Dq + tid];
        outv = acc * inv;
    } else {
        outv = g_h2sum[b * Dq + tid] * (1.f / Sq);
    }
    size_t oi = (size_t)blockIdx.x * Dq + tid;
    if (expert < 0) g_main[oi] = outv;
    else            g_dep[oi] += outv;
}

// ---------------- final blend + scalar outputs ----------------
__global__ void k_final(float* __restrict__ out) {
    size_t i = (size_t)blockIdx.x * 256 + threadIdx.x;
    if (i < BSDq) {
        float bw = g_bw[i];
        out[i] = bw * g_main[i] + (1.f - bw) * g_dep[i];
    }
    if (i == 0) {
        float mc = g_bwsum * (1.f / (float)BSDq);
        out[BSDq]     = fabsf(mc - 0.6f) * 0.01f;
        out[BSDq + 1] = mc;
    }
}

// ---------------- host launcher ----------------
extern "C" void kernel_launch(void* const* d_in, const int* in_sizes, int n_in,
                              void* d_out, int out_size) {
    const float* feature  = (const float*)d_in[0];
    const float* adj      = (const float*)d_in[1];
    const float* main_W1  = (const float*)d_in[2];
    const float* main_a1s = (const float*)d_in[3];
    const float* main_a1d = (const float*)d_in[4];
    const float* main_W2  = (const float*)d_in[5];
    const float* main_a2s = (const float*)d_in[6];
    const float* main_a2d = (const float*)d_in[7];
    const float* dep_W1   = (const float*)d_in[8];
    const float* dep_a1s  = (const float*)d_in[9];
    const float* dep_a1d  = (const float*)d_in[10];
    const float* dep_W2   = (const float*)d_in[11];
    const float* dep_a2s  = (const float*)d_in[12];
    const float* dep_a2d  = (const float*)d_in[13];
    const float* router_W = (const float*)d_in[14];
    const float* blend_W  = (const float*)d_in[15];
    const float* blend_b  = (const float*)d_in[16];
    const int*   doc_num  = (const int*)d_in[17];
    const int*   sect_num = (const int*)d_in[18];
    float* out = (float*)d_out;

    k_zero<<<(BSDq + 255) / 256, 256>>>();
    k_router<<<BSq / 4, 128>>>(feature, router_W);
    k_blend<<<BSq, 256>>>(feature, blend_W, blend_b);

    for (int e = -1; e < Eq; e++) {
        const float* W1  = (e < 0) ? main_W1  : dep_W1  + (size_t)e * Hq * Dq * HDq;
        const float* a1s = (e < 0) ? main_a1s : dep_a1s + (size_t)e * Hq * HDq;
        const float* a1d = (e < 0) ? main_a1d : dep_a1d + (size_t)e * Hq * HDq;
        const float* W2  = (e < 0) ? main_W2  : dep_W2  + (size_t)e * NHq * Dq;
        const float* a2s = (e < 0) ? main_a2s : dep_a2s + (size_t)e * Dq;
        const float* a2d = (e < 0) ? main_a2d : dep_a2d + (size_t)e * Dq;

        k_gemm_h<<<dim3(Hq, Sq / 64, Bq), 256>>>(feature, W1, e);
        k_esed<<<(Bq * Hq * Sq) / 4, 128>>>(a1s, a1d);
        k_hsum<<<Bq * Hq, HDq>>>();
        k_att1<<<BSq, 128>>>(adj, doc_num, sect_num, e);
        k_gemm_h2<<<dim3(Dq / 64, Sq / 64, Bq), 256>>>(W2);
        k_gsgd<<<BSq / 4, 128>>>(a2s, a2d);
        k_h2sum<<<Bq, Dq>>>();
        k_att2<<<BSq, 256>>>(adj, doc_num, sect_num, e);
    }

    k_final<<<(BSDq + 255) / 256, 256>>>(out);
}

// round 2
// speedup vs baseline: 2.4472x; 2.4472x over previous
#include <cuda_runtime.h>
#include <math.h>

// Fixed shapes
#define Bq 4
#define Sq 1024
#define Dq 256
#define Hq 6
#define HDq 64
#define NHq 384          // H*Hd
#define BSq 4096         // B*S
#define BSDq (BSq*Dq)
#define NEXP 4           // slot 0 = main, 1..3 = deputies

// ---------------- scratch ----------------
__device__ float g_h  [(size_t)NEXP*BSq*NHq];   // [exp][bs][h*64+o]
__device__ float g_h1 [(size_t)NEXP*BSq*NHq];
__device__ float g_h2 [(size_t)NEXP*BSq*Dq];
__device__ float g_es [NEXP*BSq*8];             // padded 8 per node
__device__ float g_ed [NEXP*BSq*8];
__device__ float g_hsum [NEXP*Bq*NHq];
__device__ float g_h2sum[NEXP*Bq*Dq];
__device__ float g_gs [NEXP*BSq];
__device__ float g_gd [NEXP*BSq];
__device__ float g_W1t[NEXP*Dq*NHq];            // [exp][k][h*64+o]
__device__ float g_main[BSDq];
__device__ float g_dep [BSDq];
__device__ float g_bw  [BSDq];
__device__ float g_bwsum;
__device__ unsigned char  g_rmask[3*BSq];
__device__ unsigned short g_lst[(size_t)BSq*Sq];
__device__ int g_cnt[BSq*4];                    // c_sent, c_sent+sect, total, 0

__device__ __forceinline__ float leaky02(float x){ return x > 0.f ? x : 0.2f*x; }
__device__ __forceinline__ float elu1(float x){ return x > 0.f ? x : expm1f(x); }
__device__ __forceinline__ unsigned f2tf(float x){ unsigned u; asm("cvt.rna.tf32.f32 %0, %1;":"=r"(u):"f"(x)); return u; }
__device__ __forceinline__ void mma_tf32(float c[4], unsigned a0,unsigned a1,unsigned a2,unsigned a3,
                                         unsigned b0,unsigned b1){
    asm volatile("mma.sync.aligned.m16n8k8.row.col.f32.tf32.tf32.f32 "
        "{%0,%1,%2,%3},{%4,%5,%6,%7},{%8,%9},{%0,%1,%2,%3};"
        : "+f"(c[0]),"+f"(c[1]),"+f"(c[2]),"+f"(c[3])
        : "r"(a0),"r"(a1),"r"(a2),"r"(a3),"r"(b0),"r"(b1));
}

// ---------------- zero init ----------------
__global__ void k_zero(){
    int i = blockIdx.x*256 + threadIdx.x;
    if (i < BSDq) g_dep[i] = 0.f;
    if (i == 0) g_bwsum = 0.f;
}

// ---------------- neighbor lists (deterministic sorted build, one adj pass) --------
__global__ void k_nbr(const float* __restrict__ adj, const int* __restrict__ dnum,
                      const int* __restrict__ snum){
    __shared__ int sc[256];
    __shared__ int ra[256], rb[256];
    int bs = blockIdx.x, tid = threadIdx.x;
    int doc = dnum[0], sect = snum[0];
    int lim1 = Sq - sect - doc, lim2 = Sq - doc;
    const float* arow = adj + (size_t)bs*Sq;
    float4 a = *(const float4*)(arow + tid*4);
    unsigned short loc[4]; int c=0, ca=0, cb=0;
    float av[4] = {a.x,a.y,a.z,a.w};
    #pragma unroll
    for (int i=0;i<4;i++){
        int col = tid*4+i;
        if (av[i] > 0.f){ loc[c++] = (unsigned short)col; ca += (col<lim1); cb += (col<lim2); }
    }
    sc[tid]=c; ra[tid]=ca; rb[tid]=cb;
    __syncthreads();
    for (int off=1; off<256; off<<=1){
        int v = (tid>=off)? sc[tid-off] : 0;
        __syncthreads();
        sc[tid]+=v;
        __syncthreads();
    }
    int base = sc[tid]-c;
    for (int i=0;i<c;i++) g_lst[(size_t)bs*Sq + base + i] = loc[i];
    for (int st=128; st>0; st>>=1){
        if (tid<st){ ra[tid]+=ra[tid+st]; rb[tid]+=rb[tid+st]; }
        __syncthreads();
    }
    if (tid==0){
        g_cnt[bs*4+0]=ra[0]; g_cnt[bs*4+1]=rb[0]; g_cnt[bs*4+2]=sc[255]; g_cnt[bs*4+3]=0;
    }
}

// ---------------- router: top-2 of 3 => exclude argmin (last idx on ties) ----------
__global__ void k_router(const float* __restrict__ x, const float* __restrict__ Wr){
    int gw   = (blockIdx.x*blockDim.x + threadIdx.x) >> 5;
    int lane = threadIdx.x & 31;
    if (gw >= BSq) return;
    const float* xr = x + (size_t)gw*Dq;
    float a0=0.f,a1=0.f,a2=0.f;
    for (int k=lane;k<Dq;k+=32){
        float xv = xr[k];
        a0 += xv*Wr[k*3+0]; a1 += xv*Wr[k*3+1]; a2 += xv*Wr[k*3+2];
    }
    #pragma unroll
    for (int o=16;o>0;o>>=1){
        a0 += __shfl_down_sync(0xffffffffu,a0,o);
        a1 += __shfl_down_sync(0xffffffffu,a1,o);
        a2 += __shfl_down_sync(0xffffffffu,a2,o);
    }
    if (lane==0){
        float v[3]={a0,a1,a2};
        int ex=0; float mv=v[0];
        #pragma unroll
        for (int e=1;e<3;e++) if (v[e]<=mv){ mv=v[e]; ex=e; }
        #pragma unroll
        for (int e=0;e<3;e++) g_rmask[e*BSq+gw] = (e==ex)?0:1;
    }
}

// ---------------- transpose W1 -> [exp][k][h*64+o] ----------------
__global__ void k_prepw(const float* __restrict__ mainW1, const float* __restrict__ depW1){
    int e = blockIdx.y;
    int i = blockIdx.x*256 + threadIdx.x;        // over Dq*NHq = 98304
    const float* src = (e==0)? mainW1 : depW1 + (size_t)(e-1)*Hq*Dq*HDq;
    int k = i/NHq, n = i%NHq, h = n>>6, o = n&63;
    g_W1t[(size_t)e*Dq*NHq + i] = src[(size_t)h*Dq*HDq + (size_t)k*HDq + o];
}

// ---------------- tf32 tensor-core GEMM: C[e] = A[e] (x mask) @ B[e] ----------------
template<int KD, int ND, bool MASK>
__global__ void __launch_bounds__(256) k_mm(const float* __restrict__ Abase, size_t astride,
                                            const float* __restrict__ Bmain,
                                            const float* __restrict__ Bdep, size_t bstride,
                                            float* __restrict__ Cbase){
    int e = blockIdx.z;
    const float* A = Abase + astride*e;
    const float* B = (e==0)? Bmain : Bdep + bstride*(e-1);
    float* C = Cbase + (size_t)e*BSq*ND;
    int m0 = blockIdx.y*128, n0 = blockIdx.x*128;
    __shared__ unsigned As[128][17];
    __shared__ unsigned Bs[16][132];
    int tid=threadIdx.x, lane=tid&31, wid=tid>>5;
    int wm=(wid&1)*64, wn=(wid>>1)*32;
    int gid=lane>>2, qid=lane&3;
    float c[4][4][4];
    #pragma unroll
    for (int mt=0;mt<4;mt++)
        #pragma unroll
        for (int nt=0;nt<4;nt++)
            #pragma unroll
            for (int r=0;r<4;r++) c[mt][nt][r]=0.f;
    int arow=tid>>1, acol=(tid&1)*8;
    int brow=tid>>4, bcol=(tid&15)*8;
    float am = 1.f;
    if (MASK){ if (e>0 && g_rmask[(size_t)(e-1)*BSq + m0 + arow]==0) am = 0.f; }
    for (int k0=0;k0<KD;k0+=16){
        float4 a0 = *(const float4*)(A + (size_t)(m0+arow)*KD + k0+acol);
        float4 a1 = *(const float4*)(A + (size_t)(m0+arow)*KD + k0+acol+4);
        float4 b0 = *(const float4*)(B + (size_t)(k0+brow)*ND + n0+bcol);
        float4 b1 = *(const float4*)(B + (size_t)(k0+brow)*ND + n0+bcol+4);
        __syncthreads();
        As[arow][acol+0]=f2tf(a0.x*am); As[arow][acol+1]=f2tf(a0.y*am);
        As[arow][acol+2]=f2tf(a0.z*am); As[arow][acol+3]=f2tf(a0.w*am);
        As[arow][acol+4]=f2tf(a1.x*am); As[arow][acol+5]=f2tf(a1.y*am);
        As[arow][acol+6]=f2tf(a1.z*am); As[arow][acol+7]=f2tf(a1.w*am);
        Bs[brow][bcol+0]=f2tf(b0.x); Bs[brow][bcol+1]=f2tf(b0.y);
        Bs[brow][bcol+2]=f2tf(b0.z); Bs[brow][bcol+3]=f2tf(b0.w);
        Bs[brow][bcol+4]=f2tf(b1.x); Bs[brow][bcol+5]=f2tf(b1.y);
        Bs[brow][bcol+6]=f2tf(b1.z); Bs[brow][bcol+7]=f2tf(b1.w);
        __syncthreads();
        #pragma unroll
        for (int kk=0;kk<16;kk+=8){
            unsigned af[4][4], bf[4][2];
            #pragma unroll
            for (int mt=0;mt<4;mt++){
                int r = wm + mt*16 + gid;
                af[mt][0]=As[r][kk+qid];   af[mt][1]=As[r+8][kk+qid];
                af[mt][2]=As[r][kk+qid+4]; af[mt][3]=As[r+8][kk+qid+4];
            }
            #pragma unroll
            for (int nt=0;nt<4;nt++){
                int cc = wn + nt*8 + gid;
                bf[nt][0]=Bs[kk+qid][cc]; bf[nt][1]=Bs[kk+qid+4][cc];
            }
            #pragma unroll
            for (int mt=0;mt<4;mt++)
                #pragma unroll
                for (int nt=0;nt<4;nt++)
                    mma_tf32(c[mt][nt], af[mt][0],af[mt][1],af[mt][2],af[mt][3],
                             bf[nt][0],bf[nt][1]);
        }
    }
    #pragma unroll
    for (int mt=0;mt<4;mt++){
        int row = m0 + wm + mt*16 + gid;
        #pragma unroll
        for (int nt=0;nt<4;nt++){
            int col = n0 + wn + nt*8 + qid*2;
            *(float2*)&C[(size_t)row*ND + col]     = make_float2(c[mt][nt][0], c[mt][nt][1]);
            *(float2*)&C[(size_t)(row+8)*ND + col] = make_float2(c[mt][nt][2], c[mt][nt][3]);
        }
    }
}

// ---------------- sigmoid + mean accumulation over blend matmul ----------------
__global__ void k_sig(const float* __restrict__ bias){
    __shared__ float red[256];
    int i = blockIdx.x*256 + threadIdx.x;
    float v = 1.f/(1.f + expf(-(g_bw[i] + bias[i & (Dq-1)])));
    g_bw[i] = v;
    red[threadIdx.x] = v;
    __syncthreads();
    for (int st=128; st>0; st>>=1){ if (threadIdx.x<st) red[threadIdx.x]+=red[threadIdx.x+st]; __syncthreads(); }
    if (threadIdx.x==0) atomicAdd(&g_bwsum, red[0]);
}

// ---------------- es/ed per (exp,bs,h) ----------------
__global__ void k_esed(const float* __restrict__ a1s_m, const float* __restrict__ a1d_m,
                       const float* __restrict__ a1s_d, const float* __restrict__ a1d_d){
    int gw   = (blockIdx.x*blockDim.x + threadIdx.x) >> 5;
    int lane = threadIdx.x & 31;
    if (gw >= NEXP*BSq*Hq) return;
    int h = gw % Hq, be = gw / Hq;      // be = e*BSq+bs
    int e = be / BSq;
    const float* as = ((e==0)? a1s_m : a1s_d + (size_t)(e-1)*NHq) + h*HDq;
    const float* ad = ((e==0)? a1d_m : a1d_d + (size_t)(e-1)*NHq) + h*HDq;
    const float* hr = g_h + (size_t)be*NHq + h*HDq;
    float s=0.f, d=0.f;
    #pragma unroll
    for (int o=lane;o<HDq;o+=32){
        float v = hr[o];
        s += v*as[o]; d += v*ad[o];
    }
    #pragma unroll
    for (int o=16;o>0;o>>=1){
        s += __shfl_down_sync(0xffffffffu,s,o);
        d += __shfl_down_sync(0xffffffffu,d,o);
    }
    if (lane==0){ g_es[be*8+h]=s; g_ed[be*8+h]=d; }
}

// ---------------- hsum[exp][b][n] = sum_s h ----------------
__global__ void k_hsum(){
    int eb = blockIdx.x;                 // e*4+b
    int e = eb>>2, b = eb&3;
    const float* base = g_h + ((size_t)e*BSq + ((size_t)b<<10))*NHq;
    int t = threadIdx.x;
    float acc = 0.f;
    for (int s=0;s<Sq;s++) acc += base[(size_t)s*NHq + t];
    g_hsum[(size_t)eb*NHq + t] = acc;
}

// ---------------- attention layer 1 (all 6 heads in one pass) ----------------
__global__ void __launch_bounds__(128) k_att1(){
    __shared__ unsigned short lst[1024];
    __shared__ unsigned char  ok[1024];
    __shared__ float w[6*1024];
    __shared__ float red[6*128];
    __shared__ float es6[6];
    int bs = blockIdx.x, ex = blockIdx.y, b = bs>>10;
    int tid = threadIdx.x;
    int c1 = g_cnt[bs*4+0], c2 = g_cnt[bs*4+1], ct = g_cnt[bs*4+2];
    int lo, hi;
    if      (ex==0){ lo=0;  hi=ct; }
    else if (ex==1){ lo=0;  hi=c1; }
    else if (ex==2){ lo=c1; hi=c2; }
    else           { lo=c2; hi=ct; }
    int n = hi-lo;
    float* h1row = g_h1 + ((size_t)ex*BSq + bs)*NHq;
    if (n==0){
        if (tid<96){
            float4 hv = *(const float4*)&g_hsum[(size_t)((ex<<2)|b)*NHq + tid*4];
            float4 o;
            o.x=elu1(hv.x*(1.f/Sq)); o.y=elu1(hv.y*(1.f/Sq));
            o.z=elu1(hv.z*(1.f/Sq)); o.w=elu1(hv.w*(1.f/Sq));
            *(float4*)&h1row[tid*4]=o;
        }
        return;
    }
    for (int j=tid;j<n;j+=128) lst[j] = g_lst[(size_t)bs*Sq + lo + j];
    if (tid<6) es6[tid] = g_es[((size_t)ex*BSq + bs)*8 + tid];
    __syncthreads();
    const float* edb = g_ed + ((size_t)ex*BSq + ((size_t)b<<10))*8;
    const unsigned char* rm = (ex>0)? g_rmask + (size_t)(ex-1)*BSq + (b<<10) : nullptr;
    float mx[6];
    #pragma unroll
    for (int h=0;h<6;h++) mx[h] = -1e30f;
    for (int j=tid;j<n;j+=128){
        int nb = lst[j];
        float4 e0 = *(const float4*)&edb[nb*8];
        float2 e1 = *(const float2*)&edb[nb*8+4];
        ok[j] = rm ? rm[nb] : 1;
        float ev[6] = {e0.x,e0.y,e0.z,e0.w,e1.x,e1.y};
        #pragma unroll
        for (int h=0;h<6;h++){
            float e = leaky02(es6[h] + ev[h]);
            w[h*1024+j] = e;
            mx[h] = fmaxf(mx[h], e);
        }
    }
    #pragma unroll
    for (int h=0;h<6;h++) red[h*128+tid]=mx[h];
    __syncthreads();
    for (int st=64;st>0;st>>=1){
        if (tid<st){
            #pragma unroll
            for (int h=0;h<6;h++) red[h*128+tid]=fmaxf(red[h*128+tid], red[h*128+tid+st]);
        }
        __syncthreads();
    }
    float mxv[6];
    #pragma unroll
    for (int h=0;h<6;h++) mxv[h]=red[h*128];
    __syncthreads();
    float sm[6] = {0.f,0.f,0.f,0.f,0.f,0.f};
    for (int j=tid;j<n;j+=128){
        #pragma unroll
        for (int h=0;h<6;h++){
            float ww = expf(w[h*1024+j]-mxv[h]);
            w[h*1024+j]=ww;
            sm[h]+=ww;
        }
    }
    #pragma unroll
    for (int h=0;h<6;h++) red[h*128+tid]=sm[h];
    __syncthreads();
    for (int st=64;st>0;st>>=1){
        if (tid<st){
            #pragma unroll
            for (int h=0;h<6;h++) red[h*128+tid]+=red[h*128+tid+st];
        }
        __syncthreads();
    }
    if (tid<96){
        int h = tid>>4;
        float inv = 1.f/red[h*128];
        const float* hb = g_h + ((size_t)ex*BSq + ((size_t)b<<10))*NHq;
        float ax=0.f, ay=0.f, az=0.f, aw=0.f;
        for (int j=0;j<n;j++){
            if (!ok[j]) continue;
            float wv = w[h*1024+j];
            float4 hv = *(const float4*)&hb[(size_t)lst[j]*NHq + tid*4];
            ax += wv*hv.x; ay += wv*hv.y; az += wv*hv.z; aw += wv*hv.w;
        }
        float4 o;
        o.x=elu1(ax*inv); o.y=elu1(ay*inv); o.z=elu1(az*inv); o.w=elu1(aw*inv);
        *(float4*)&h1row[tid*4]=o;
    }
}

// ---------------- gs/gd per (exp,bs) ----------------
__global__ void k_gsgd(const float* __restrict__ a2s_m, const float* __restrict__ a2d_m,
                       const float* __restrict__ a2s_d, const float* __restrict__ a2d_d){
    int gw   = (blockIdx.x*blockDim.x + threadIdx.x) >> 5;
    int lane = threadIdx.x & 31;
    if (gw >= NEXP*BSq) return;
    int e = gw / BSq;
    const float* as = (e==0)? a2s_m : a2s_d + (size_t)(e-1)*Dq;
    const float* ad = (e==0)? a2d_m : a2d_d + (size_t)(e-1)*Dq;
    const float* hr = g_h2 + (size_t)gw*Dq;
    float s=0.f, d=0.f;
    #pragma unroll
    for (int k=lane;k<Dq;k+=32){
        float v = hr[k];
        s += v*as[k]; d += v*ad[k];
    }
    #pragma unroll
    for (int o=16;o>0;o>>=1){
        s += __shfl_down_sync(0xffffffffu,s,o);
        d += __shfl_down_sync(0xffffffffu,d,o);
    }
    if (lane==0){ g_gs[gw]=s; g_gd[gw]=d; }
}

// ---------------- h2sum[exp][b][d] ----------------
__global__ void k_h2sum(){
    int eb = blockIdx.x;
    int e = eb>>2, b = eb&3;
    const float* base = g_h2 + ((size_t)e*BSq + ((size_t)b<<10))*Dq;
    int t = threadIdx.x;
    float acc = 0.f;
    for (int s=0;s<Sq;s++) acc += base[(size_t)s*Dq + t];
    g_h2sum[(size_t)eb*Dq + t] = acc;
}

// ---------------- attention layer 2 ----------------
__global__ void __launch_bounds__(256) k_att2(){
    __shared__ unsigned short lst[1024];
    __shared__ float w[1024];
    __shared__ float red[256];
    __shared__ float4 sacc[4][64];
    int bs = blockIdx.x, ex = blockIdx.y, b = bs>>10;
    int tid = threadIdx.x;
    if (ex>0 && g_rmask[(size_t)(ex-1)*BSq + bs]==0) return;
    int c1 = g_cnt[bs*4+0], c2 = g_cnt[bs*4+1], ct = g_cnt[bs*4+2];
    int lo, hi;
    if      (ex==0){ lo=0;  hi=ct; }
    else if (ex==1){ lo=0;  hi=c1; }
    else if (ex==2){ lo=c1; hi=c2; }
    else           { lo=c2; hi=ct; }
    int n = hi-lo;
    if (n==0){
        if (tid<64){
            float4 hv = *(const float4*)&g_h2sum[(size_t)((ex<<2)|b)*Dq + tid*4];
            float4 o = make_float4(hv.x*(1.f/Sq), hv.y*(1.f/Sq), hv.z*(1.f/Sq), hv.w*(1.f/Sq));
            if (ex==0) *(float4*)&g_main[(size_t)bs*Dq + tid*4] = o;
            else {
                float* dp = &g_dep[(size_t)bs*Dq + tid*4];
                atomicAdd(dp+0,o.x); atomicAdd(dp+1,o.y); atomicAdd(dp+2,o.z); atomicAdd(dp+3,o.w);
            }
        }
        return;
    }
    for (int j=tid;j<n;j+=256) lst[j] = g_lst[(size_t)bs*Sq + lo + j];
    __syncthreads();
    float gsv = g_gs[(size_t)ex*BSq + bs];
    const float* gdb = g_gd + (size_t)ex*BSq + (b<<10);
    float mloc = -1e30f;
    for (int j=tid;j<n;j+=256){
        float e = leaky02(gsv + gdb[lst[j]]);
        w[j]=e;
        mloc = fmaxf(mloc,e);
    }
    red[tid]=mloc; __syncthreads();
    for (int st=128;st>0;st>>=1){ if (tid<st) red[tid]=fmaxf(red[tid],red[tid+st]); __syncthreads(); }
    float m = red[0]; __syncthreads();
    float sloc = 0.f;
    for (int j=tid;j<n;j+=256){ float ww=expf(w[j]-m); w[j]=ww; sloc+=ww; }
    red[tid]=sloc; __syncthreads();
    for (int st=128;st>0;st>>=1){ if (tid<st) red[tid]+=red[tid+st]; __syncthreads(); }
    float inv = 1.f/red[0];
    int grp = tid>>6, q = tid&63;
    const float* h2b = g_h2 + ((size_t)ex*BSq + ((size_t)b<<10))*Dq;
    float ax=0.f, ay=0.f, az=0.f, aw=0.f;
    for (int j=grp;j<n;j+=4){
        float wv = w[j];
        float4 hv = *(const float4*)&h2b[(size_t)lst[j]*Dq + q*4];
        ax += wv*hv.x; ay += wv*hv.y; az += wv*hv.z; aw += wv*hv.w;
    }
    sacc[grp][q] = make_float4(ax,ay,az,aw);
    __syncthreads();
    if (tid<64){
        float4 a0=sacc[0][tid], a1=sacc[1][tid], a2=sacc[2][tid], a3=sacc[3][tid];
        float4 o = make_float4((a0.x+a1.x+a2.x+a3.x)*inv, (a0.y+a1.y+a2.y+a3.y)*inv,
                               (a0.z+a1.z+a2.z+a3.z)*inv, (a0.w+a1.w+a2.w+a3.w)*inv);
        if (ex==0) *(float4*)&g_main[(size_t)bs*Dq + tid*4] = o;
        else {
            float* dp = &g_dep[(size_t)bs*Dq + tid*4];
            atomicAdd(dp+0,o.x); atomicAdd(dp+1,o.y); atomicAdd(dp+2,o.z); atomicAdd(dp+3,o.w);
        }
    }
}

// ---------------- final blend + scalars ----------------
__global__ void k_final(float* __restrict__ out){
    size_t i = (size_t)blockIdx.x*256 + threadIdx.x;
    if (i < BSDq){
        float bw = g_bw[i];
        out[i] = bw*g_main[i] + (1.f-bw)*g_dep[i];
    }
    if (i == 0){
        float mc = g_bwsum * (1.f/(float)BSDq);
        out[BSDq]   = fabsf(mc - 0.6f) * 0.01f;
        out[BSDq+1] = mc;
    }
}

// ---------------- host launcher ----------------
extern "C" void kernel_launch(void* const* d_in, const int* in_sizes, int n_in,
                              void* d_out, int out_size){
    const float* feature  = (const float*)d_in[0];
    const float* adj      = (const float*)d_in[1];
    const float* main_W1  = (const float*)d_in[2];
    const float* main_a1s = (const float*)d_in[3];
    const float* main_a1d = (const float*)d_in[4];
    const float* main_W2  = (const float*)d_in[5];
    const float* main_a2s = (const float*)d_in[6];
    const float* main_a2d = (const float*)d_in[7];
    const float* dep_W1   = (const float*)d_in[8];
    const float* dep_a1s  = (const float*)d_in[9];
    const float* dep_a1d  = (const float*)d_in[10];
    const float* dep_W2   = (const float*)d_in[11];
    const float* dep_a2s  = (const float*)d_in[12];
    const float* dep_a2d  = (const float*)d_in[13];
    const float* router_W = (const float*)d_in[14];
    const float* blend_W  = (const float*)d_in[15];
    const float* blend_b  = (const float*)d_in[16];
    const int*   doc_num  = (const int*)d_in[17];
    const int*   sect_num = (const int*)d_in[18];
    float* out = (float*)d_out;

    float* g_W1t_p; cudaGetSymbolAddress((void**)&g_W1t_p, g_W1t);
    float* g_h1_p;  cudaGetSymbolAddress((void**)&g_h1_p,  g_h1);
    float* g_h_p;   cudaGetSymbolAddress((void**)&g_h_p,   g_h);
    float* g_h2_p;  cudaGetSymbolAddress((void**)&g_h2_p,  g_h2);
    float* g_bw_p;  cudaGetSymbolAddress((void**)&g_bw_p,  g_bw);

    k_zero<<<(BSDq+255)/256, 256>>>();
    k_nbr<<<BSq, 256>>>(adj, doc_num, sect_num);
    k_router<<<BSq/4, 128>>>(feature, router_W);
    k_prepw<<<dim3(Dq*NHq/256, NEXP), 256>>>(main_W1, dep_W1);

    // blend matmul (pre-sigmoid) on tensor cores, then sigmoid+mean
    k_mm<Dq, Dq, false><<<dim3(2,32,1), 256>>>(feature, 0, blend_W, blend_W, 0, g_bw_p);
    k_sig<<<BSDq/256, 256>>>(blend_b);

    // layer-1 GEMM all experts
    k_mm<Dq, NHq, true><<<dim3(3,32,NEXP), 256>>>(feature, 0, g_W1t_p,
                                                  g_W1t_p + (size_t)Dq*NHq, (size_t)Dq*NHq, g_h_p);
    k_esed<<<(NEXP*BSq*Hq)/8, 256>>>(main_a1s, main_a1d, dep_a1s, dep_a1d);
    k_hsum<<<NEXP*Bq, NHq>>>();
    k_att1<<<dim3(BSq, NEXP), 128>>>();

    // layer-2 GEMM all experts
    k_mm<NHq, Dq, false><<<dim3(2,32,NEXP), 256>>>(g_h1_p, (size_t)BSq*NHq, main_W2,
                                                   dep_W2, (size_t)NHq*Dq, g_h2_p);
    k_gsgd<<<(NEXP*BSq)/8, 256>>>(main_a2s, main_a2d, dep_a2s, dep_a2d);
    k_h2sum<<<NEXP*Bq, Dq>>>();
    k_att2<<<dim3(BSq, NEXP), 256>>>();

    k_final<<<(BSDq+255)/256, 256>>>(out);
}